// round 5
// baseline (speedup 1.0000x reference)
#include <cuda_runtime.h>
#include <cstdint>
#include <math_constants.h>

#define BB     2
#define NN     8192
#define KK     10
#define KS     11          // KK + 1 slot to absorb self
#define TPB    128
#define TILE   1024
#define SEG    2
#define SEGLEN (NN / SEG)  // 4096
#define CAP    8           // per-lane staging slots

// Scratch (no device allocation allowed)
__device__ float4 g_ptsA[BB * NN];             // {x, y, z, |p|^2}        (query form)
__device__ float4 g_ptsB[BB * NN];             // {-2x, -2y, -2z, |p|^2} (candidate form)
__device__ float4 g_q[BB * NN];                // {p1-p2, 0}
__device__ float  g_top_d[SEG * BB * NN * KS];
__device__ int    g_top_i[SEG * BB * NN * KS];
__device__ float  g_acc;
__device__ unsigned int g_bdone;

__global__ void prep_kernel(const float* __restrict__ p1,
                            const float* __restrict__ p2) {
    int i = blockIdx.x * blockDim.x + threadIdx.x;
    if (i == 0) { g_acc = 0.0f; g_bdone = 0u; }
    if (i < BB * NN) {
        float x = p1[3 * i + 0], y = p1[3 * i + 1], z = p1[3 * i + 2];
        float a = p2[3 * i + 0], b = p2[3 * i + 1], c = p2[3 * i + 2];
        float w = fmaf(z, z, fmaf(y, y, x * x));
        g_ptsA[i] = make_float4(x, y, z, w);
        g_ptsB[i] = make_float4(-2.0f * x, -2.0f * y, -2.0f * z, w);
        g_q[i]    = make_float4(x - a, y - b, z - c, 0.0f);
    }
}

// Branchless sorted insert into ascending 11-list. Inserting +inf is a no-op.
__device__ __forceinline__ void insert11(float v, int vi,
                                         float* __restrict__ dist,
                                         int* __restrict__ nn) {
    bool p[KS];
#pragma unroll
    for (int k = 0; k < KS; ++k) p[k] = v < dist[k];
#pragma unroll
    for (int k = KS - 1; k >= 1; --k) {
        dist[k] = p[k] ? (p[k - 1] ? dist[k - 1] : v) : dist[k];
        nn[k]   = p[k] ? (p[k - 1] ? nn[k - 1]  : vi) : nn[k];
    }
    dist[0] = p[0] ? v  : dist[0];
    nn[0]   = p[0] ? vi : nn[0];
}

// grid: (NN/TPB, BB, SEG). One thread per query; scans SEGLEN candidates.
__global__ __launch_bounds__(TPB) void knn_seg_kernel() {
    __shared__ float4 tile[TILE];
    __shared__ float2 buf[CAP][TPB];   // per-lane staging: {d2, idx-bits}

    const int b  = blockIdx.y;
    const int s  = blockIdx.z;
    const int qi = blockIdx.x * TPB + threadIdx.x;
    const int c0 = s * SEGLEN;
    const float4* __restrict__ cand = g_ptsB + b * NN;

    const float4 me = g_ptsA[b * NN + qi];

    float dist[KS];
    int   nn[KS];
#pragma unroll
    for (int k = 0; k < KS; ++k) {
        dist[k] = CUDART_INF_F;
        nn[k]   = -1;
    }

    float thr = CUDART_INF_F;
    int   cnt = 0;

    for (int t = c0; t < c0 + SEGLEN; t += TILE) {
#pragma unroll
        for (int j = threadIdx.x; j < TILE; j += TPB)
            tile[j] = cand[t + j];
        __syncthreads();

        for (int j0 = 0; j0 < TILE; j0 += 4) {
#pragma unroll
            for (int u = 0; u < 4; ++u) {
                float4 c = tile[j0 + u];
                float d2 = fmaf(c.x, me.x,
                           fmaf(c.y, me.y,
                           fmaf(c.z, me.z, me.w + c.w)));
                if (d2 < thr) {   // predicated store, no warp machinery
                    buf[cnt][threadIdx.x] =
                        make_float2(d2, __int_as_float(t + j0 + u));
                    ++cnt;
                }
            }
            if (__any_sync(0xffffffffu, cnt > CAP - 4)) {
                int mx = __reduce_max_sync(0xffffffffu, cnt);
                for (int r = 0; r < mx; ++r) {   // mx is warp-uniform
                    float2 e = buf[r][threadIdx.x];
                    float v  = (r < cnt) ? e.x : CUDART_INF_F;
                    insert11(v, __float_as_int(e.y), dist, nn);
                }
                cnt = 0;
                thr = dist[KS - 1];
            }
        }
        __syncthreads();
    }

    {   // final flush
        int mx = __reduce_max_sync(0xffffffffu, cnt);
        for (int r = 0; r < mx; ++r) {
            float2 e = buf[r][threadIdx.x];
            float v  = (r < cnt) ? e.x : CUDART_INF_F;
            insert11(v, __float_as_int(e.y), dist, nn);
        }
    }

    long base = (((long)s * BB + b) * NN + qi) * KS;
#pragma unroll
    for (int k = 0; k < KS; ++k) {
        g_top_d[base + k] = dist[k];
        g_top_i[base + k] = nn[k];
    }
}

// One thread per query: 2-way merge of sorted 11-lists, skip self, take 10,
// then L1-loss contribution; last block finalizes the output.
__global__ __launch_bounds__(256) void merge_loss_kernel(float* __restrict__ out,
                                                         int nblocks) {
    __shared__ float wsum[256 / 32];

    int q  = blockIdx.x * blockDim.x + threadIdx.x;
    int b  = q / NN;
    int qi = q - b * NN;

    long base0 = (((long)0 * BB + b) * NN + qi) * KS;
    long base1 = (((long)1 * BB + b) * NN + qi) * KS;

    float hd0 = g_top_d[base0], hd1 = g_top_d[base1];
    int   hi0 = g_top_i[base0], hi1 = g_top_i[base1];
    int   p0 = 1, p1 = 1;

    const float4* __restrict__ qv = g_q + b * NN;
    float sx = 0.0f, sy = 0.0f, sz = 0.0f;
    int cnt = 0;

#pragma unroll
    for (int step = 0; step < KS + 1; ++step) {
        if (cnt >= KK) break;
        int idx;
        if (hd1 < hd0) {             // tie -> list 0 (lower indices) wins
            idx = hi1;
            hd1 = (p1 < KS) ? g_top_d[base1 + p1] : CUDART_INF_F;
            hi1 = (p1 < KS) ? g_top_i[base1 + p1] : -1;
            ++p1;
        } else {
            idx = hi0;
            hd0 = (p0 < KS) ? g_top_d[base0 + p0] : CUDART_INF_F;
            hi0 = (p0 < KS) ? g_top_i[base0 + p0] : -1;
            ++p0;
        }
        if (idx != qi && idx >= 0) {
            float4 v = __ldg(&qv[idx]);
            sx += v.x; sy += v.y; sz += v.z;
            ++cnt;
        }
    }

    float4 myq = qv[qi];
    const float inv_k = 1.0f / (float)KK;
    float lx = sx * inv_k - myq.x;
    float ly = sy * inv_k - myq.y;
    float lz = sz * inv_k - myq.z;
    float contrib = fabsf(lx) + fabsf(ly) + fabsf(lz);

#pragma unroll
    for (int off = 16; off > 0; off >>= 1)
        contrib += __shfl_down_sync(0xffffffffu, contrib, off);
    if ((threadIdx.x & 31) == 0) wsum[threadIdx.x >> 5] = contrib;
    __syncthreads();
    if (threadIdx.x == 0) {
        float ssum = 0.0f;
#pragma unroll
        for (int w = 0; w < 256 / 32; ++w) ssum += wsum[w];
        atomicAdd(&g_acc, ssum);
        __threadfence();
        unsigned int done = atomicAdd(&g_bdone, 1u);
        if (done == (unsigned int)(nblocks - 1)) {
            float acc = *((volatile float*)&g_acc);
            out[0] = acc * (1.0f / (float)(BB * NN * 3));
        }
    }
}

extern "C" void kernel_launch(void* const* d_in, const int* in_sizes, int n_in,
                              void* d_out, int out_size) {
    const float* p1 = (const float*)d_in[0];
    const float* p2 = (const float*)d_in[1];
    float* out = (float*)d_out;

    prep_kernel<<<(BB * NN + 255) / 256, 256>>>(p1, p2);
    dim3 grid(NN / TPB, BB, SEG);
    knn_seg_kernel<<<grid, TPB>>>();
    int nblocks = BB * NN / 256;
    merge_loss_kernel<<<nblocks, 256>>>(out, nblocks);
}